// round 10
// baseline (speedup 1.0000x reference)
#include <cuda_runtime.h>
#include <math.h>

namespace {

constexpr int B = 128;
constexpr int N = 2048;
constexpr int E = 32768;
constexpr int BN = B * N;             // 262144 nodes
constexpr int CAP = 64;               // max edges/node (Poisson(16); P(>=64) ~ 1e-20)
constexpr float INV_SQRT_DH = 0.7071067811865476f;

// Scratch (device globals — no allocations allowed)
__device__ float g_h[BN * 4];               // node state (h1 then h2), 4 MB
__device__ int   g_cursor[BN];              // per-node degree counter, 1 MB
__device__ int4  g_pay[(CAP / 2) * BN];     // slot-pair-major buckets, 134 MB
                                            // pair i of node n at g_pay[i*BN+n]
                                            // = {srcA, timeA, srcB, timeB}

// Weights in constant memory (filled by capturable D2D copies each launch)
__constant__ float cWq[2 * 16];
__constant__ float cWk[2 * 32];
__constant__ float cWv[2 * 32];
__constant__ float cWo[2 * 16];
__constant__ float cbo[2 * 4];
__constant__ float ctw[4];
__constant__ float ctb[4];
__constant__ float cWlin[24];
__constant__ float cblin[2];

// ---------------------------------------------------------------------------
// Zero the degree counters.
// ---------------------------------------------------------------------------
__global__ void __launch_bounds__(256) zero_cursor() {
    int idx = blockIdx.x * blockDim.x + threadIdx.x;
    reinterpret_cast<int4*>(g_cursor)[idx] = make_int4(0, 0, 0, 0);
}

// ---------------------------------------------------------------------------
// Scatter: bucket every edge by dst. 4 edges per thread, vector loads.
// 1 scalar RED (cursor) + 1 STG.64 (payload half-pair) per edge.
// ---------------------------------------------------------------------------
constexpr int SC_THREADS = 256;
constexpr int SC_EPT = 4;
constexpr int SC_GROUPS_PER_B = E / SC_EPT;        // 8192 = 2^13

__global__ void __launch_bounds__(SC_THREADS) scatter_kernel(
        const int*   __restrict__ edge_index,
        const float* __restrict__ edge_time) {
    int gid = blockIdx.x * SC_THREADS + threadIdx.x;   // 0 .. B*E/4-1
    int b = gid >> 13;
    int e = (gid & (SC_GROUPS_PER_B - 1)) * SC_EPT;

    const int* ei = edge_index + (size_t)b * 2 * E;
    int4   s4 = __ldg(reinterpret_cast<const int4*>(ei + e));
    int4   d4 = __ldg(reinterpret_cast<const int4*>(ei + E + e));
    float4 t4 = __ldg(reinterpret_cast<const float4*>(edge_time + (size_t)b * E + e));

    int nb = b * N;
    int src[4] = {s4.x, s4.y, s4.z, s4.w};
    int dst[4] = {d4.x, d4.y, d4.z, d4.w};
    float tt[4] = {t4.x, t4.y, t4.z, t4.w};
#pragma unroll
    for (int i = 0; i < 4; i++) {
        int node = nb + dst[i];
        int pos = atomicAdd(&g_cursor[node], 1);
        if (pos < CAP) {
            int2* half = reinterpret_cast<int2*>(&g_pay[(size_t)(pos >> 1) * BN + node]);
            half[pos & 1] = make_int2(src[i], __float_as_int(tt[i]));
        }
    }
}

// ---------------------------------------------------------------------------
// Gather pass for layer L: stage per-batch kh/vh tiles (64 KB) in smem; each
// thread owns one dst node and walks its bucket 2 edges at a time with a
// depth-1 software prefetch. Zero atomics; fused node update.
// ---------------------------------------------------------------------------
constexpr int G_THREADS = 256;
constexpr int GPB = N / G_THREADS;     // 8 blocks per batch
constexpr int G_SMEM = 2 * N * 16;     // 64 KB

__device__ __forceinline__ void edge_accum(
        const float4* __restrict__ skh, const float4* __restrict__ svh,
        const float* __restrict__ WkB, const float* __restrict__ WvB,
        const float* __restrict__ q,
        int src, float dt,
        float& s0, float& s1, float& a0, float& a1, float& a2, float& a3) {
    float phi[4];
#pragma unroll
    for (int j = 0; j < 4; j++) phi[j] = __cosf(fmaf(dt, ctw[j], ctb[j]));

    float4 kh4 = skh[src];
    float k0 = kh4.x, k1 = kh4.y, k2 = kh4.z, k3 = kh4.w;
#pragma unroll
    for (int j = 0; j < 4; j++) {
        k0 = fmaf(phi[j], WkB[j * 4 + 0], k0);
        k1 = fmaf(phi[j], WkB[j * 4 + 1], k1);
        k2 = fmaf(phi[j], WkB[j * 4 + 2], k2);
        k3 = fmaf(phi[j], WkB[j * 4 + 3], k3);
    }

    float l0 = fmaf(q[0], k0, q[1] * k1);
    float l1 = fmaf(q[2], k2, q[3] * k3);
    float p0 = __expf(fminf(l0, 80.0f));
    float p1 = __expf(fminf(l1, 80.0f));

    float4 vh4 = svh[src];
    float v0 = vh4.x, v1 = vh4.y, v2 = vh4.z, v3 = vh4.w;
#pragma unroll
    for (int j = 0; j < 4; j++) {
        v0 = fmaf(phi[j], WvB[j * 4 + 0], v0);
        v1 = fmaf(phi[j], WvB[j * 4 + 1], v1);
        v2 = fmaf(phi[j], WvB[j * 4 + 2], v2);
        v3 = fmaf(phi[j], WvB[j * 4 + 3], v3);
    }

    s0 += p0;
    s1 += p1;
    a0 = fmaf(p0, v0, a0);
    a1 = fmaf(p0, v1, a1);
    a2 = fmaf(p1, v2, a2);
    a3 = fmaf(p1, v3, a3);
}

template <int L>
__global__ void __launch_bounds__(G_THREADS) gather_pass(
        const float* __restrict__ x,
        const float* __restrict__ timestamp) {
    extern __shared__ float4 smem[];
    float4* skh = smem;        // h@Wk_top per node
    float4* svh = smem + N;    // h@Wv_top per node

    int b     = blockIdx.x >> 3;
    int chunk = blockIdx.x & 7;

    int n = chunk * G_THREADS + threadIdx.x;
    int gnode = b * N + n;

    // Kick off this thread's first payload load & degree ASAP.
    int deg = min(g_cursor[gnode], CAP);
    int pairs = (deg + 1) >> 1;
    const int4* pay = g_pay + gnode;
    int4 cur = make_int4(0, 0, 0, 0);
    if (pairs > 0) cur = __ldg(pay);

    const float4* hsrc = (L == 0 ? reinterpret_cast<const float4*>(x)
                                 : reinterpret_cast<const float4*>(g_h)) + b * N;

    const float* WkT = cWk + L * 32;        // rows 0..3 (h part)
    const float* WvT = cWv + L * 32;
    const float* WkB = cWk + L * 32 + 16;   // rows 4..7 (phi part)
    const float* WvB = cWv + L * 32 + 16;
    const float* Wq  = cWq + L * 16;

    // Stage kh/vh for the whole batch (coalesced reads, tiny redundant FMA).
    for (int i = threadIdx.x; i < N; i += G_THREADS) {
        float4 h = hsrc[i];
        float kh[4], vh[4];
#pragma unroll
        for (int j = 0; j < 4; j++) {
            float a = h.x * WkT[0 * 4 + j];
            a = fmaf(h.y, WkT[1 * 4 + j], a);
            a = fmaf(h.z, WkT[2 * 4 + j], a);
            a = fmaf(h.w, WkT[3 * 4 + j], a);
            kh[j] = a;
            float c = h.x * WvT[0 * 4 + j];
            c = fmaf(h.y, WvT[1 * 4 + j], c);
            c = fmaf(h.z, WvT[2 * 4 + j], c);
            c = fmaf(h.w, WvT[3 * 4 + j], c);
            vh[j] = c;
        }
        skh[i] = make_float4(kh[0], kh[1], kh[2], kh[3]);
        svh[i] = make_float4(vh[0], vh[1], vh[2], vh[3]);
    }
    __syncthreads();

    float4 hn = hsrc[n];
    float q[4];
#pragma unroll
    for (int j = 0; j < 4; j++) {
        float a = hn.x * Wq[0 * 4 + j];
        a = fmaf(hn.y, Wq[1 * 4 + j], a);
        a = fmaf(hn.z, Wq[2 * 4 + j], a);
        a = fmaf(hn.w, Wq[3 * 4 + j], a);
        q[j] = a * INV_SQRT_DH;
    }

    float ts = __ldg(timestamp + b);

    float s0 = 0.f, s1 = 0.f;
    float a0 = 0.f, a1 = 0.f, a2 = 0.f, a3 = 0.f;

    // Walk the bucket: 2 edges per iteration, prefetch next pair (MLP >= 2).
    for (int i = 0; i < pairs; i++) {
        int4 nxt = cur;
        if (i + 1 < pairs) nxt = __ldg(pay + (size_t)(i + 1) * BN);

        edge_accum(skh, svh, WkB, WvB, q,
                   cur.x, ts - __int_as_float(cur.y),
                   s0, s1, a0, a1, a2, a3);
        if (2 * i + 1 < deg) {
            edge_accum(skh, svh, WkB, WvB, q,
                       cur.z, ts - __int_as_float(cur.w),
                       s0, s1, a0, a1, a2, a3);
        }
        cur = nxt;
    }

    // Fused node update: h_next = relu(h + (agg/s) @ Wo + bo)
    float r0 = (s0 == 0.0f) ? 1.0f : __frcp_rn(s0);
    float r1 = (s1 == 0.0f) ? 1.0f : __frcp_rn(s1);
    float at0 = a0 * r0, at1 = a1 * r0;
    float at2 = a2 * r1, at3 = a3 * r1;

    const float* Wo = cWo + L * 16;
    const float* bo = cbo + L * 4;
    float hin[4] = {hn.x, hn.y, hn.z, hn.w};
    float hout[4];
#pragma unroll
    for (int j = 0; j < 4; j++) {
        float v = hin[j] + bo[j];
        v = fmaf(at0, Wo[0 * 4 + j], v);
        v = fmaf(at1, Wo[1 * 4 + j], v);
        v = fmaf(at2, Wo[2 * 4 + j], v);
        v = fmaf(at3, Wo[3 * 4 + j], v);
        hout[j] = fmaxf(v, 0.0f);
    }
    reinterpret_cast<float4*>(g_h)[gnode] =
        make_float4(hout[0], hout[1], hout[2], hout[3]);
}

// ---------------------------------------------------------------------------
// Final head: feats = [h[src_idx], h[dst_idx], cos(ts*w+b)] @ W_lin + b_lin
// ---------------------------------------------------------------------------
__global__ void final_kernel(const int*   __restrict__ src_index,
                             const int*   __restrict__ dst_index,
                             const float* __restrict__ timestamp,
                             float* __restrict__ out) {
    int b = threadIdx.x;
    if (b >= B) return;

    float4 hs = reinterpret_cast<const float4*>(g_h)[b * N + src_index[b]];
    float4 hd = reinterpret_cast<const float4*>(g_h)[b * N + dst_index[b]];
    float ts = timestamp[b];

    float f[12];
    f[0] = hs.x; f[1] = hs.y; f[2] = hs.z; f[3] = hs.w;
    f[4] = hd.x; f[5] = hd.y; f[6] = hd.z; f[7] = hd.w;
#pragma unroll
    for (int j = 0; j < 4; j++) f[8 + j] = cosf(fmaf(ts, ctw[j], ctb[j]));

#pragma unroll
    for (int k = 0; k < 2; k++) {
        float acc = cblin[k];
#pragma unroll
        for (int i = 0; i < 12; i++) acc = fmaf(f[i], cWlin[i * 2 + k], acc);
        out[b * 2 + k] = acc;
    }
}

} // anonymous namespace

extern "C" void kernel_launch(void* const* d_in, const int* in_sizes, int n_in,
                              void* d_out, int out_size) {
    const float* x          = (const float*)d_in[0];
    const int*   edge_index = (const int*)  d_in[1];
    const float* edge_time  = (const float*)d_in[2];
    const float* timestamp  = (const float*)d_in[3];
    const int*   src_index  = (const int*)  d_in[4];
    const int*   dst_index  = (const int*)  d_in[5];
    float* out = (float*)d_out;

    // Allow 64 KB dynamic smem for the gather kernels (host-side, idempotent).
    static bool attr_set = false;
    if (!attr_set) {
        cudaFuncSetAttribute(gather_pass<0>,
            cudaFuncAttributeMaxDynamicSharedMemorySize, G_SMEM);
        cudaFuncSetAttribute(gather_pass<1>,
            cudaFuncAttributeMaxDynamicSharedMemorySize, G_SMEM);
        attr_set = true;
    }

    // Stage all weights into constant memory (device-to-device, capturable).
    cudaMemcpyToSymbolAsync(cWq,   d_in[8],  2 * 16 * 4, 0, cudaMemcpyDeviceToDevice);
    cudaMemcpyToSymbolAsync(cWk,   d_in[9],  2 * 32 * 4, 0, cudaMemcpyDeviceToDevice);
    cudaMemcpyToSymbolAsync(cWv,   d_in[10], 2 * 32 * 4, 0, cudaMemcpyDeviceToDevice);
    cudaMemcpyToSymbolAsync(cWo,   d_in[11], 2 * 16 * 4, 0, cudaMemcpyDeviceToDevice);
    cudaMemcpyToSymbolAsync(cbo,   d_in[12], 2 * 4 * 4,  0, cudaMemcpyDeviceToDevice);
    cudaMemcpyToSymbolAsync(ctw,   d_in[6],  4 * 4,      0, cudaMemcpyDeviceToDevice);
    cudaMemcpyToSymbolAsync(ctb,   d_in[7],  4 * 4,      0, cudaMemcpyDeviceToDevice);
    cudaMemcpyToSymbolAsync(cWlin, d_in[13], 24 * 4,     0, cudaMemcpyDeviceToDevice);
    cudaMemcpyToSymbolAsync(cblin, d_in[14], 2 * 4,      0, cudaMemcpyDeviceToDevice);

    zero_cursor<<<BN / (256 * 4), 256>>>();

    scatter_kernel<<<(B * E) / (SC_THREADS * SC_EPT), SC_THREADS>>>(
        edge_index, edge_time);

    gather_pass<0><<<B * GPB, G_THREADS, G_SMEM>>>(x, timestamp);
    gather_pass<1><<<B * GPB, G_THREADS, G_SMEM>>>(x, timestamp);

    final_kernel<<<1, 128>>>(src_index, dst_index, timestamp, out);
}

// round 12
// speedup vs baseline: 1.1200x; 1.1200x over previous
#include <cuda_runtime.h>
#include <math.h>

namespace {

constexpr int B = 128;
constexpr int N = 2048;
constexpr int E = 32768;
constexpr int BN = B * N;             // 262144 nodes
constexpr int CAP = 64;               // max edges/node (12-sigma over Binomial mean 16)
constexpr int PAIRS = CAP / 2;        // 32 int4 pairs per node
constexpr float INV_SQRT_DH = 0.7071067811865476f;

// Scratch (device globals — no allocations allowed)
__device__ float g_h1[BN * 4];                   // layer-0 output, 4 MB
__device__ float g_h2[BN * 4];                   // layer-1 output, 4 MB
__device__ int   g_cursor[BN];                   // per-node degree, 1 MB
__device__ int4  g_pay[(size_t)PAIRS * BN];      // node-major buckets, 134 MB

// Weights in constant memory (filled by capturable D2D copies each launch)
__constant__ float cWq[2 * 16];
__constant__ float cWk[2 * 32];
__constant__ float cWv[2 * 32];
__constant__ float cWo[2 * 16];
__constant__ float cbo[2 * 4];
__constant__ float ctw[4];
__constant__ float ctb[4];
__constant__ float cWlin[24];
__constant__ float cblin[2];

// ---------------------------------------------------------------------------
// Zero the degree counters.
// ---------------------------------------------------------------------------
__global__ void __launch_bounds__(256) zero_cursor() {
    int idx = blockIdx.x * blockDim.x + threadIdx.x;
    reinterpret_cast<int4*>(g_cursor)[idx] = make_int4(0, 0, 0, 0);
}

// ---------------------------------------------------------------------------
// Scatter: bucket every edge by dst. 8 edges per thread, vector loads.
// 1 scalar RED (cursor) + 1 STG.64 per edge. Runs ONCE for both layers.
// ---------------------------------------------------------------------------
constexpr int SC_THREADS = 256;
constexpr int SC_EPT = 8;
constexpr int SC_GROUPS_PER_B = E / SC_EPT;        // 4096 = 2^12

__global__ void __launch_bounds__(SC_THREADS) scatter_kernel(
        const int*   __restrict__ edge_index,
        const float* __restrict__ edge_time) {
    int gid = blockIdx.x * SC_THREADS + threadIdx.x;   // 0 .. B*E/8-1
    int b = gid >> 12;
    int e = (gid & (SC_GROUPS_PER_B - 1)) * SC_EPT;

    const int* ei = edge_index + (size_t)b * 2 * E;
    int4   s4a = __ldg(reinterpret_cast<const int4*>(ei + e));
    int4   s4b = __ldg(reinterpret_cast<const int4*>(ei + e + 4));
    int4   d4a = __ldg(reinterpret_cast<const int4*>(ei + E + e));
    int4   d4b = __ldg(reinterpret_cast<const int4*>(ei + E + e + 4));
    float4 t4a = __ldg(reinterpret_cast<const float4*>(edge_time + (size_t)b * E + e));
    float4 t4b = __ldg(reinterpret_cast<const float4*>(edge_time + (size_t)b * E + e + 4));

    int nb = b * N;
    int src[8] = {s4a.x, s4a.y, s4a.z, s4a.w, s4b.x, s4b.y, s4b.z, s4b.w};
    int dst[8] = {d4a.x, d4a.y, d4a.z, d4a.w, d4b.x, d4b.y, d4b.z, d4b.w};
    float tt[8] = {t4a.x, t4a.y, t4a.z, t4a.w, t4b.x, t4b.y, t4b.z, t4b.w};
#pragma unroll
    for (int i = 0; i < 8; i++) {
        int node = nb + dst[i];
        int pos = atomicAdd(&g_cursor[node], 1);
        if (pos < CAP) {
            int2* half = reinterpret_cast<int2*>(
                &g_pay[(size_t)node * PAIRS + (pos >> 1)]);
            half[pos & 1] = make_int2(src[i], __float_as_int(tt[i]));
        }
    }
}

// ---------------------------------------------------------------------------
// Gather pass for layer L: 2 threads per node (even/odd pairs), node-major
// payload so a node's bucket is 1-4 cache lines. No smem, no atomics.
// Reads h_in, writes h_out (double-buffered; no in-place race).
// ---------------------------------------------------------------------------
constexpr int G_THREADS = 256;   // 128 nodes per block

template <int L>
__global__ void __launch_bounds__(G_THREADS) gather_pass(
        const float* __restrict__ h_in,      // layer input states (x or g_h1)
        float*       __restrict__ h_out,     // layer output states
        const float* __restrict__ timestamp) {
    int t = blockIdx.x * G_THREADS + threadIdx.x;
    int node = t >> 1;               // global node id
    int sub  = t & 1;                // 0: even pairs, 1: odd pairs
    int b = node >> 11;              // N = 2048

    const float4* hsrc = reinterpret_cast<const float4*>(h_in);

    int deg = min(__ldg(&g_cursor[node]), CAP);
    int Pt = (deg + 1) >> 1;                       // total pairs
    const int4* pay = g_pay + (size_t)node * PAIRS;

    // Prefetch this lane's first pair ASAP.
    int i = sub;
    int4 cur = make_int4(0, 0, 0, 0);
    if (i < Pt) cur = __ldg(pay + i);

    const float* Wk = cWk + L * 32;
    const float* Wv = cWv + L * 32;
    const float* Wq = cWq + L * 16;

    float4 hn = __ldg(hsrc + node);
    float q[4];
#pragma unroll
    for (int j = 0; j < 4; j++) {
        float a = hn.x * Wq[0 * 4 + j];
        a = fmaf(hn.y, Wq[1 * 4 + j], a);
        a = fmaf(hn.z, Wq[2 * 4 + j], a);
        a = fmaf(hn.w, Wq[3 * 4 + j], a);
        q[j] = a * INV_SQRT_DH;
    }
    float ts = __ldg(timestamp + b);
    const float4* hbatch = hsrc + b * N;

    float s0 = 0.f, s1 = 0.f;
    float a0 = 0.f, a1 = 0.f, a2 = 0.f, a3 = 0.f;

    for (; i < Pt; i += 2) {
        int4 nxt = cur;
        if (i + 2 < Pt) nxt = __ldg(pay + i + 2);

#pragma unroll
        for (int half = 0; half < 2; half++) {
            int eidx = 2 * i + half;
            if (eidx >= deg) break;
            int src   = half == 0 ? cur.x : cur.z;
            int tbits = half == 0 ? cur.y : cur.w;
            float dt = ts - __int_as_float(tbits);

            float4 hs = __ldg(hbatch + src);
            float msg[8];
            msg[0] = hs.x; msg[1] = hs.y; msg[2] = hs.z; msg[3] = hs.w;
#pragma unroll
            for (int j = 0; j < 4; j++)
                msg[4 + j] = __cosf(fmaf(dt, ctw[j], ctb[j]));

            float k[4];
#pragma unroll
            for (int j = 0; j < 4; j++) {
                float acc = msg[0] * Wk[0 * 4 + j];
#pragma unroll
                for (int r = 1; r < 8; r++) acc = fmaf(msg[r], Wk[r * 4 + j], acc);
                k[j] = acc;
            }

            float l0 = fmaf(q[0], k[0], q[1] * k[1]);
            float l1 = fmaf(q[2], k[2], q[3] * k[3]);
            float p0 = __expf(fminf(l0, 80.0f));
            float p1 = __expf(fminf(l1, 80.0f));

            float v[4];
#pragma unroll
            for (int j = 0; j < 4; j++) {
                float acc = msg[0] * Wv[0 * 4 + j];
#pragma unroll
                for (int r = 1; r < 8; r++) acc = fmaf(msg[r], Wv[r * 4 + j], acc);
                v[j] = acc;
            }

            s0 += p0;
            s1 += p1;
            a0 = fmaf(p0, v[0], a0);
            a1 = fmaf(p0, v[1], a1);
            a2 = fmaf(p1, v[2], a2);
            a3 = fmaf(p1, v[3], a3);
        }
        cur = nxt;
    }

    // Combine the two lanes of this node.
    s0 += __shfl_xor_sync(0xffffffffu, s0, 1);
    s1 += __shfl_xor_sync(0xffffffffu, s1, 1);
    a0 += __shfl_xor_sync(0xffffffffu, a0, 1);
    a1 += __shfl_xor_sync(0xffffffffu, a1, 1);
    a2 += __shfl_xor_sync(0xffffffffu, a2, 1);
    a3 += __shfl_xor_sync(0xffffffffu, a3, 1);

    if (sub == 0) {
        float r0 = (s0 == 0.0f) ? 1.0f : __frcp_rn(s0);
        float r1 = (s1 == 0.0f) ? 1.0f : __frcp_rn(s1);
        float at0 = a0 * r0, at1 = a1 * r0;
        float at2 = a2 * r1, at3 = a3 * r1;

        const float* Wo = cWo + L * 16;
        const float* bo = cbo + L * 4;
        float hin[4] = {hn.x, hn.y, hn.z, hn.w};
        float hout[4];
#pragma unroll
        for (int j = 0; j < 4; j++) {
            float v = hin[j] + bo[j];
            v = fmaf(at0, Wo[0 * 4 + j], v);
            v = fmaf(at1, Wo[1 * 4 + j], v);
            v = fmaf(at2, Wo[2 * 4 + j], v);
            v = fmaf(at3, Wo[3 * 4 + j], v);
            hout[j] = fmaxf(v, 0.0f);
        }
        reinterpret_cast<float4*>(h_out)[node] =
            make_float4(hout[0], hout[1], hout[2], hout[3]);
    }
}

// ---------------------------------------------------------------------------
// Final head: feats = [h2[src_idx], h2[dst_idx], cos(ts*w+b)] @ W_lin + b_lin
// ---------------------------------------------------------------------------
__global__ void final_kernel(const int*   __restrict__ src_index,
                             const int*   __restrict__ dst_index,
                             const float* __restrict__ timestamp,
                             float* __restrict__ out) {
    int b = threadIdx.x;
    if (b >= B) return;

    float4 hs = reinterpret_cast<const float4*>(g_h2)[b * N + src_index[b]];
    float4 hd = reinterpret_cast<const float4*>(g_h2)[b * N + dst_index[b]];
    float ts = timestamp[b];

    float f[12];
    f[0] = hs.x; f[1] = hs.y; f[2] = hs.z; f[3] = hs.w;
    f[4] = hd.x; f[5] = hd.y; f[6] = hd.z; f[7] = hd.w;
#pragma unroll
    for (int j = 0; j < 4; j++) f[8 + j] = cosf(fmaf(ts, ctw[j], ctb[j]));

#pragma unroll
    for (int k = 0; k < 2; k++) {
        float acc = cblin[k];
#pragma unroll
        for (int i = 0; i < 12; i++) acc = fmaf(f[i], cWlin[i * 2 + k], acc);
        out[b * 2 + k] = acc;
    }
}

} // anonymous namespace

extern "C" void kernel_launch(void* const* d_in, const int* in_sizes, int n_in,
                              void* d_out, int out_size) {
    const float* x          = (const float*)d_in[0];
    const int*   edge_index = (const int*)  d_in[1];
    const float* edge_time  = (const float*)d_in[2];
    const float* timestamp  = (const float*)d_in[3];
    const int*   src_index  = (const int*)  d_in[4];
    const int*   dst_index  = (const int*)  d_in[5];
    float* out = (float*)d_out;

    // Stage all weights into constant memory (device-to-device, capturable).
    cudaMemcpyToSymbolAsync(cWq,   d_in[8],  2 * 16 * 4, 0, cudaMemcpyDeviceToDevice);
    cudaMemcpyToSymbolAsync(cWk,   d_in[9],  2 * 32 * 4, 0, cudaMemcpyDeviceToDevice);
    cudaMemcpyToSymbolAsync(cWv,   d_in[10], 2 * 32 * 4, 0, cudaMemcpyDeviceToDevice);
    cudaMemcpyToSymbolAsync(cWo,   d_in[11], 2 * 16 * 4, 0, cudaMemcpyDeviceToDevice);
    cudaMemcpyToSymbolAsync(cbo,   d_in[12], 2 * 4 * 4,  0, cudaMemcpyDeviceToDevice);
    cudaMemcpyToSymbolAsync(ctw,   d_in[6],  4 * 4,      0, cudaMemcpyDeviceToDevice);
    cudaMemcpyToSymbolAsync(ctb,   d_in[7],  4 * 4,      0, cudaMemcpyDeviceToDevice);
    cudaMemcpyToSymbolAsync(cWlin, d_in[13], 24 * 4,     0, cudaMemcpyDeviceToDevice);
    cudaMemcpyToSymbolAsync(cblin, d_in[14], 2 * 4,      0, cudaMemcpyDeviceToDevice);

    zero_cursor<<<BN / (256 * 4), 256>>>();

    scatter_kernel<<<(B * E) / (SC_THREADS * SC_EPT), SC_THREADS>>>(
        edge_index, edge_time);

    // 2 threads per node -> 2*BN threads total. Double-buffered states.
    float* d_h1;
    float* d_h2;
    cudaGetSymbolAddress((void**)&d_h1, g_h1);
    cudaGetSymbolAddress((void**)&d_h2, g_h2);

    gather_pass<0><<<(2 * BN) / G_THREADS, G_THREADS>>>(x, d_h1, timestamp);
    gather_pass<1><<<(2 * BN) / G_THREADS, G_THREADS>>>(d_h1, d_h2, timestamp);

    final_kernel<<<1, 128>>>(src_index, dst_index, timestamp, out);
}

// round 13
// speedup vs baseline: 3.7560x; 3.3537x over previous
#include <cuda_runtime.h>
#include <math.h>

namespace {

constexpr int B = 128;
constexpr int N = 2048;
constexpr int E = 32768;
constexpr int LIST_CAP = 384;          // edges per output node (mean ~16, 60+ sigma safe)
constexpr float INV_SQRT_DH = 0.7071067811865476f;

// Per-batch bitmap of "needed h1" nodes (64 words x 32 bits = 2048 nodes), 32 KB
__device__ unsigned g_bitmap[B * 64];

// Weights in constant memory (filled by capturable D2D copies each launch)
__constant__ float cWq[2 * 16];
__constant__ float cWk[2 * 32];
__constant__ float cWv[2 * 32];
__constant__ float cWo[2 * 16];
__constant__ float cbo[2 * 4];
__constant__ float ctw[4];
__constant__ float ctb[4];
__constant__ float cWlin[24];
__constant__ float cblin[2];

// ---------------------------------------------------------------------------
// K1: build the needed-node bitmap for each batch.
// Marks src of every edge whose dst is an output node, plus the output nodes.
// One block per batch; streams the dst column (128 KB/block).
// ---------------------------------------------------------------------------
__global__ void __launch_bounds__(1024) mark_kernel(
        const int* __restrict__ edge_index,
        const int* __restrict__ src_index,
        const int* __restrict__ dst_index) {
    __shared__ unsigned bm[64];
    int b = blockIdx.x;
    int tid = threadIdx.x;
    if (tid < 64) bm[tid] = 0u;
    __syncthreads();

    int out0 = __ldg(src_index + b);
    int out1 = __ldg(dst_index + b);
    const int* ei = edge_index + (size_t)b * 2 * E;
    const int4* dst4 = reinterpret_cast<const int4*>(ei + E);

#pragma unroll
    for (int i = tid; i < E / 4; i += 1024) {
        int4 d = __ldg(dst4 + i);
        int e = i * 4;
        if (d.x == out0 || d.x == out1) { int s = __ldg(ei + e);     atomicOr(&bm[s >> 5], 1u << (s & 31)); }
        if (d.y == out0 || d.y == out1) { int s = __ldg(ei + e + 1); atomicOr(&bm[s >> 5], 1u << (s & 31)); }
        if (d.z == out0 || d.z == out1) { int s = __ldg(ei + e + 2); atomicOr(&bm[s >> 5], 1u << (s & 31)); }
        if (d.w == out0 || d.w == out1) { int s = __ldg(ei + e + 3); atomicOr(&bm[s >> 5], 1u << (s & 31)); }
    }
    __syncthreads();
    if (tid == 0) {
        bm[out0 >> 5] |= 1u << (out0 & 31);
        bm[out1 >> 5] |= 1u << (out1 & 31);
    }
    __syncthreads();
    if (tid < 64) g_bitmap[b * 64 + tid] = bm[tid];
}

// ---------------------------------------------------------------------------
// K2: everything else, one block per batch.
// smem: x-tile (32KB, becomes h1 in place), per-node acc (48KB), bitmap,
// per-output-node edge lists. Streams the dst column once; only edges whose
// dst is marked (~550 of 32768) take the heavy path.
// ---------------------------------------------------------------------------
constexpr int K2_THREADS = 1024;
constexpr size_t SM_SX    = 0;                         // float4[2048]   32768 B
constexpr size_t SM_SACC  = 2048 * 4;                  // float[2048*6]  49152 B (float idx)
constexpr size_t SM_TOTAL_FLOATS = 2048 * 4 + 2048 * 6;
constexpr size_t K2_SMEM_BYTES =
    SM_TOTAL_FLOATS * 4 + 64 * 4 + 2 * 4 + 2 * LIST_CAP * 8 + 16;

__global__ void __launch_bounds__(K2_THREADS) solve_kernel(
        const float* __restrict__ x,
        const int*   __restrict__ edge_index,
        const float* __restrict__ edge_time,
        const float* __restrict__ timestamp,
        const int*   __restrict__ src_index,
        const int*   __restrict__ dst_index,
        float* __restrict__ out) {
    extern __shared__ float smem[];
    float4*   sx    = reinterpret_cast<float4*>(smem);          // x then h1
    float*    sacc  = smem + SM_SACC;                           // 6 per node
    unsigned* sbm   = reinterpret_cast<unsigned*>(smem + SM_TOTAL_FLOATS);
    int*      scnt  = reinterpret_cast<int*>(sbm + 64);
    int2*     slist = reinterpret_cast<int2*>(scnt + 4);        // [2][LIST_CAP]

    int b = blockIdx.x;
    int tid = threadIdx.x;

    // --- init smem ---
    if (tid < 64) sbm[tid] = g_bitmap[b * 64 + tid];
    if (tid < 2) scnt[tid] = 0;
    {   // zero acc (12288 floats = 3072 float4)
        float4* sacc4 = reinterpret_cast<float4*>(sacc);
        for (int i = tid; i < 3072; i += K2_THREADS)
            sacc4[i] = make_float4(0.f, 0.f, 0.f, 0.f);
    }
    {   // stage x tile
        const float4* x4 = reinterpret_cast<const float4*>(x) + b * N;
        for (int i = tid; i < N; i += K2_THREADS) sx[i] = x4[i];
    }
    __syncthreads();

    int out0 = __ldg(src_index + b);
    int out1 = __ldg(dst_index + b);
    float ts = __ldg(timestamp + b);
    const int* ei = edge_index + (size_t)b * 2 * E;
    const float* et = edge_time + (size_t)b * E;
    const int4* dst4 = reinterpret_cast<const int4*>(ei + E);

    // --- scan: layer-0 attention for edges whose dst is marked ---
    for (int i = tid; i < E / 4; i += K2_THREADS) {
        int4 d4 = __ldg(dst4 + i);
        int ebase = i * 4;
        int dd[4] = {d4.x, d4.y, d4.z, d4.w};
#pragma unroll
        for (int u = 0; u < 4; u++) {
            int dstn = dd[u];
            if (!((sbm[dstn >> 5] >> (dstn & 31)) & 1u)) continue;
            int e = ebase + u;
            int src = __ldg(ei + e);
            float tv = __ldg(et + e);

            // record layer-1 edges for the output nodes
            if (dstn == out0) {
                int p = atomicAdd(&scnt[0], 1);
                if (p < LIST_CAP) slist[p] = make_int2(src, __float_as_int(tv));
            } else if (dstn == out1) {
                int p = atomicAdd(&scnt[1], 1);
                if (p < LIST_CAP) slist[LIST_CAP + p] = make_int2(src, __float_as_int(tv));
            }

            // layer-0 edge math (h0 = x)
            float dt = ts - tv;
            float4 hs = sx[src];
            float msg[8];
            msg[0] = hs.x; msg[1] = hs.y; msg[2] = hs.z; msg[3] = hs.w;
#pragma unroll
            for (int j = 0; j < 4; j++) msg[4 + j] = __cosf(fmaf(dt, ctw[j], ctb[j]));

            float k[4];
#pragma unroll
            for (int j = 0; j < 4; j++) {
                float acc = msg[0] * cWk[0 * 4 + j];
#pragma unroll
                for (int r = 1; r < 8; r++) acc = fmaf(msg[r], cWk[r * 4 + j], acc);
                k[j] = acc;
            }
            float4 hd = sx[dstn];
            float q[4];
#pragma unroll
            for (int j = 0; j < 4; j++) {
                float a = hd.x * cWq[0 * 4 + j];
                a = fmaf(hd.y, cWq[1 * 4 + j], a);
                a = fmaf(hd.z, cWq[2 * 4 + j], a);
                a = fmaf(hd.w, cWq[3 * 4 + j], a);
                q[j] = a * INV_SQRT_DH;
            }
            float l0 = fmaf(q[0], k[0], q[1] * k[1]);
            float l1 = fmaf(q[2], k[2], q[3] * k[3]);
            float p0 = __expf(fminf(l0, 80.0f));
            float p1 = __expf(fminf(l1, 80.0f));

            float v[4];
#pragma unroll
            for (int j = 0; j < 4; j++) {
                float acc = msg[0] * cWv[0 * 4 + j];
#pragma unroll
                for (int r = 1; r < 8; r++) acc = fmaf(msg[r], cWv[r * 4 + j], acc);
                v[j] = acc;
            }
            float* na = sacc + dstn * 6;
            atomicAdd(na + 0, p0);
            atomicAdd(na + 1, p1);
            atomicAdd(na + 2, p0 * v[0]);
            atomicAdd(na + 3, p0 * v[1]);
            atomicAdd(na + 4, p1 * v[2]);
            atomicAdd(na + 5, p1 * v[3]);
        }
    }
    __syncthreads();

    // --- h1 for marked nodes, in place over the x tile ---
    for (int n = tid; n < N; n += K2_THREADS) {
        if (!((sbm[n >> 5] >> (n & 31)) & 1u)) continue;
        const float* na = sacc + n * 6;
        float s0 = na[0], s1 = na[1];
        float r0 = (s0 == 0.0f) ? 1.0f : __frcp_rn(s0);
        float r1 = (s1 == 0.0f) ? 1.0f : __frcp_rn(s1);
        float at0 = na[2] * r0, at1 = na[3] * r0;
        float at2 = na[4] * r1, at3 = na[5] * r1;
        float4 xv = sx[n];
        float hin[4] = {xv.x, xv.y, xv.z, xv.w};
        float h1[4];
#pragma unroll
        for (int j = 0; j < 4; j++) {
            float vv = hin[j] + cbo[j];
            vv = fmaf(at0, cWo[0 * 4 + j], vv);
            vv = fmaf(at1, cWo[1 * 4 + j], vv);
            vv = fmaf(at2, cWo[2 * 4 + j], vv);
            vv = fmaf(at3, cWo[3 * 4 + j], vv);
            h1[j] = fmaxf(vv, 0.0f);
        }
        sx[n] = make_float4(h1[0], h1[1], h1[2], h1[3]);
    }
    __syncthreads();

    // --- layer 1: only the 2 output nodes. Reuse sacc[0..11]. ---
    if (tid < 12) sacc[tid] = 0.0f;
    __syncthreads();

    int cnt0 = min(scnt[0], LIST_CAP);
    int cnt1 = min(scnt[1], LIST_CAP);
    const float* WkL = cWk + 32;
    const float* WvL = cWv + 32;
    const float* WqL = cWq + 16;

    for (int j = tid; j < cnt0 + cnt1; j += K2_THREADS) {
        int which = (j < cnt0) ? 0 : 1;
        int2 pl = (which == 0) ? slist[j] : slist[LIST_CAP + (j - cnt0)];
        int outn = (which == 0) ? out0 : out1;

        int src = pl.x;
        float dt = ts - __int_as_float(pl.y);
        float4 hs = sx[src];                 // h1[src]
        float msg[8];
        msg[0] = hs.x; msg[1] = hs.y; msg[2] = hs.z; msg[3] = hs.w;
#pragma unroll
        for (int r = 0; r < 4; r++) msg[4 + r] = __cosf(fmaf(dt, ctw[r], ctb[r]));

        float k[4];
#pragma unroll
        for (int c = 0; c < 4; c++) {
            float acc = msg[0] * WkL[0 * 4 + c];
#pragma unroll
            for (int r = 1; r < 8; r++) acc = fmaf(msg[r], WkL[r * 4 + c], acc);
            k[c] = acc;
        }
        float4 hd = sx[outn];                // h1[out]
        float q[4];
#pragma unroll
        for (int c = 0; c < 4; c++) {
            float a = hd.x * WqL[0 * 4 + c];
            a = fmaf(hd.y, WqL[1 * 4 + c], a);
            a = fmaf(hd.z, WqL[2 * 4 + c], a);
            a = fmaf(hd.w, WqL[3 * 4 + c], a);
            q[c] = a * INV_SQRT_DH;
        }
        float l0 = fmaf(q[0], k[0], q[1] * k[1]);
        float l1 = fmaf(q[2], k[2], q[3] * k[3]);
        float p0 = __expf(fminf(l0, 80.0f));
        float p1 = __expf(fminf(l1, 80.0f));

        float v[4];
#pragma unroll
        for (int c = 0; c < 4; c++) {
            float acc = msg[0] * WvL[0 * 4 + c];
#pragma unroll
            for (int r = 1; r < 8; r++) acc = fmaf(msg[r], WvL[r * 4 + c], acc);
            v[c] = acc;
        }
        float* na = sacc + which * 6;
        atomicAdd(na + 0, p0);
        atomicAdd(na + 1, p1);
        atomicAdd(na + 2, p0 * v[0]);
        atomicAdd(na + 3, p0 * v[1]);
        atomicAdd(na + 4, p1 * v[2]);
        atomicAdd(na + 5, p1 * v[3]);
    }
    __syncthreads();

    // --- final head (thread 0) ---
    if (tid == 0) {
        float f[12];
        const float* WoL = cWo + 16;
        const float* boL = cbo + 4;
#pragma unroll
        for (int w = 0; w < 2; w++) {
            int outn = (w == 0) ? out0 : out1;
            const float* na = sacc + w * 6;
            float s0 = na[0], s1 = na[1];
            float r0 = (s0 == 0.0f) ? 1.0f : __frcp_rn(s0);
            float r1 = (s1 == 0.0f) ? 1.0f : __frcp_rn(s1);
            float at0 = na[2] * r0, at1 = na[3] * r0;
            float at2 = na[4] * r1, at3 = na[5] * r1;
            float4 h1v = sx[outn];
            float hin[4] = {h1v.x, h1v.y, h1v.z, h1v.w};
#pragma unroll
            for (int j = 0; j < 4; j++) {
                float vv = hin[j] + boL[j];
                vv = fmaf(at0, WoL[0 * 4 + j], vv);
                vv = fmaf(at1, WoL[1 * 4 + j], vv);
                vv = fmaf(at2, WoL[2 * 4 + j], vv);
                vv = fmaf(at3, WoL[3 * 4 + j], vv);
                f[w * 4 + j] = fmaxf(vv, 0.0f);
            }
        }
#pragma unroll
        for (int j = 0; j < 4; j++) f[8 + j] = cosf(fmaf(ts, ctw[j], ctb[j]));
#pragma unroll
        for (int c = 0; c < 2; c++) {
            float acc = cblin[c];
#pragma unroll
            for (int i = 0; i < 12; i++) acc = fmaf(f[i], cWlin[i * 2 + c], acc);
            out[b * 2 + c] = acc;
        }
    }
}

} // anonymous namespace

extern "C" void kernel_launch(void* const* d_in, const int* in_sizes, int n_in,
                              void* d_out, int out_size) {
    const float* x          = (const float*)d_in[0];
    const int*   edge_index = (const int*)  d_in[1];
    const float* edge_time  = (const float*)d_in[2];
    const float* timestamp  = (const float*)d_in[3];
    const int*   src_index  = (const int*)  d_in[4];
    const int*   dst_index  = (const int*)  d_in[5];
    float* out = (float*)d_out;

    // Allow ~88 KB dynamic smem for K2 (host-side, idempotent).
    static bool attr_set = false;
    if (!attr_set) {
        cudaFuncSetAttribute(solve_kernel,
            cudaFuncAttributeMaxDynamicSharedMemorySize, (int)K2_SMEM_BYTES);
        attr_set = true;
    }

    // Stage all weights into constant memory (device-to-device, capturable).
    cudaMemcpyToSymbolAsync(cWq,   d_in[8],  2 * 16 * 4, 0, cudaMemcpyDeviceToDevice);
    cudaMemcpyToSymbolAsync(cWk,   d_in[9],  2 * 32 * 4, 0, cudaMemcpyDeviceToDevice);
    cudaMemcpyToSymbolAsync(cWv,   d_in[10], 2 * 32 * 4, 0, cudaMemcpyDeviceToDevice);
    cudaMemcpyToSymbolAsync(cWo,   d_in[11], 2 * 16 * 4, 0, cudaMemcpyDeviceToDevice);
    cudaMemcpyToSymbolAsync(cbo,   d_in[12], 2 * 4 * 4,  0, cudaMemcpyDeviceToDevice);
    cudaMemcpyToSymbolAsync(ctw,   d_in[6],  4 * 4,      0, cudaMemcpyDeviceToDevice);
    cudaMemcpyToSymbolAsync(ctb,   d_in[7],  4 * 4,      0, cudaMemcpyDeviceToDevice);
    cudaMemcpyToSymbolAsync(cWlin, d_in[13], 24 * 4,     0, cudaMemcpyDeviceToDevice);
    cudaMemcpyToSymbolAsync(cblin, d_in[14], 2 * 4,      0, cudaMemcpyDeviceToDevice);

    mark_kernel<<<B, 1024>>>(edge_index, src_index, dst_index);
    solve_kernel<<<B, K2_THREADS, K2_SMEM_BYTES>>>(
        x, edge_index, edge_time, timestamp, src_index, dst_index, out);
}

// round 14
// speedup vs baseline: 3.9077x; 1.0404x over previous
#include <cuda_runtime.h>
#include <math.h>

namespace {

constexpr int B = 128;
constexpr int N = 2048;
constexpr int E = 32768;
constexpr int BN = B * N;
constexpr int SPLIT = 8;                   // blocks per batch for edge scans
constexpr int CHUNK = E / SPLIT;           // 4096 edges per block
constexpr int LIST_CAP = 384;              // layer-1 edges per output node
constexpr float INV_SQRT_DH = 0.7071067811865476f;

// Scratch (device globals — no allocations allowed)
__device__ unsigned g_bitmap[B * 64];                  // needed-node bitmap, 32 KB
__device__ int      g_cnt[B * 2];                      // layer-1 list counters
__device__ float    g_acc[(size_t)BN * 8];             // [agg0..3 | s0 s1 | pad2]
__device__ int2     g_list[(size_t)B * 2 * LIST_CAP];  // layer-1 edge lists, 786 KB

// Weights in constant memory (filled by capturable D2D copies each launch)
__constant__ float cWq[2 * 16];
__constant__ float cWk[2 * 32];
__constant__ float cWv[2 * 32];
__constant__ float cWo[2 * 16];
__constant__ float cbo[2 * 4];
__constant__ float ctw[4];
__constant__ float ctb[4];
__constant__ float cWlin[24];
__constant__ float cblin[2];

// ---------------------------------------------------------------------------
// Zero: reset bitmap + counters; pre-mark output nodes and zero their acc.
// ---------------------------------------------------------------------------
__global__ void __launch_bounds__(64) zero_kernel(
        const int* __restrict__ src_index,
        const int* __restrict__ dst_index) {
    int b = blockIdx.x, t = threadIdx.x;
    g_bitmap[b * 64 + t] = 0u;
    __syncthreads();
    if (t == 0) {
        g_cnt[b * 2 + 0] = 0;
        g_cnt[b * 2 + 1] = 0;
        int out0 = src_index[b];
        int out1 = dst_index[b];
        unsigned* bm = g_bitmap + b * 64;
        bm[out0 >> 5] |= 1u << (out0 & 31);
        bm[out1 >> 5] |= 1u << (out1 & 31);
        float4* acc4 = reinterpret_cast<float4*>(g_acc) + (size_t)b * N * 2;
        float4 z = make_float4(0.f, 0.f, 0.f, 0.f);
        acc4[out0 * 2 + 0] = z; acc4[out0 * 2 + 1] = z;
        acc4[out1 * 2 + 0] = z; acc4[out1 * 2 + 1] = z;
    }
}

// ---------------------------------------------------------------------------
// Mark: stream dst column; for edges into output nodes, mark src in the
// bitmap. The unique 0->1 marker also zeroes that node's accumulator.
// B*SPLIT blocks x 256 threads.
// ---------------------------------------------------------------------------
__global__ void __launch_bounds__(256) mark_kernel(
        const int* __restrict__ edge_index,
        const int* __restrict__ src_index,
        const int* __restrict__ dst_index) {
    int blk = blockIdx.x;
    int b = blk >> 3, chunk = blk & 7;
    int out0 = __ldg(src_index + b);
    int out1 = __ldg(dst_index + b);
    const int* ei = edge_index + (size_t)b * 2 * E;
    const int* srcp = ei + chunk * CHUNK;
    const int4* dst4 = reinterpret_cast<const int4*>(ei + E + chunk * CHUNK);
    unsigned* bm = g_bitmap + b * 64;
    float4* acc4 = reinterpret_cast<float4*>(g_acc) + (size_t)b * N * 2;

    for (int i = threadIdx.x; i < CHUNK / 4; i += 256) {
        int4 d = __ldg(dst4 + i);
        int dd[4] = {d.x, d.y, d.z, d.w};
#pragma unroll
        for (int u = 0; u < 4; u++) {
            if (dd[u] == out0 || dd[u] == out1) {
                int s = __ldg(srcp + i * 4 + u);
                unsigned bit = 1u << (s & 31);
                unsigned old = atomicOr(&bm[s >> 5], bit);
                if (!(old & bit)) {
                    float4 z = make_float4(0.f, 0.f, 0.f, 0.f);
                    acc4[s * 2 + 0] = z;
                    acc4[s * 2 + 1] = z;
                }
            }
        }
    }
}

// ---------------------------------------------------------------------------
// Scan: stream dst column; marked-dst edges do layer-0 attention into the
// global acc (vector REDs) and output-node edges are appended to the
// layer-1 lists. B*SPLIT blocks x 256 threads.
// ---------------------------------------------------------------------------
__global__ void __launch_bounds__(256) scan_kernel(
        const float* __restrict__ x,
        const int*   __restrict__ edge_index,
        const float* __restrict__ edge_time,
        const float* __restrict__ timestamp,
        const int*   __restrict__ src_index,
        const int*   __restrict__ dst_index) {
    __shared__ unsigned sbm[64];
    int blk = blockIdx.x;
    int b = blk >> 3, chunk = blk & 7;
    if (threadIdx.x < 64) sbm[threadIdx.x] = g_bitmap[b * 64 + threadIdx.x];
    __syncthreads();

    int out0 = __ldg(src_index + b);
    int out1 = __ldg(dst_index + b);
    float ts = __ldg(timestamp + b);
    const int* ei = edge_index + (size_t)b * 2 * E;
    const int* srcp = ei + chunk * CHUNK;
    const float* etp = edge_time + (size_t)b * E + chunk * CHUNK;
    const int4* dst4 = reinterpret_cast<const int4*>(ei + E + chunk * CHUNK);
    const float4* xb = reinterpret_cast<const float4*>(x) + b * N;
    float* accb = g_acc + (size_t)b * N * 8;

    for (int i = threadIdx.x; i < CHUNK / 4; i += 256) {
        int4 d = __ldg(dst4 + i);
        int dd[4] = {d.x, d.y, d.z, d.w};
#pragma unroll
        for (int u = 0; u < 4; u++) {
            int dstn = dd[u];
            if (!((sbm[dstn >> 5] >> (dstn & 31)) & 1u)) continue;
            int src = __ldg(srcp + i * 4 + u);
            float tv = __ldg(etp + i * 4 + u);

            // layer-1 edge lists (non-exclusive: handles out0 == out1)
            if (dstn == out0) {
                int p = atomicAdd(&g_cnt[b * 2 + 0], 1);
                if (p < LIST_CAP)
                    g_list[(size_t)(b * 2 + 0) * LIST_CAP + p] =
                        make_int2(src, __float_as_int(tv));
            }
            if (dstn == out1) {
                int p = atomicAdd(&g_cnt[b * 2 + 1], 1);
                if (p < LIST_CAP)
                    g_list[(size_t)(b * 2 + 1) * LIST_CAP + p] =
                        make_int2(src, __float_as_int(tv));
            }

            // layer-0 edge math (h0 = x)
            float dt = ts - tv;
            float4 hs = __ldg(xb + src);
            float msg[8];
            msg[0] = hs.x; msg[1] = hs.y; msg[2] = hs.z; msg[3] = hs.w;
#pragma unroll
            for (int j = 0; j < 4; j++) msg[4 + j] = __cosf(fmaf(dt, ctw[j], ctb[j]));

            float k[4];
#pragma unroll
            for (int j = 0; j < 4; j++) {
                float acc = msg[0] * cWk[0 * 4 + j];
#pragma unroll
                for (int r = 1; r < 8; r++) acc = fmaf(msg[r], cWk[r * 4 + j], acc);
                k[j] = acc;
            }
            float4 hd = __ldg(xb + dstn);
            float q[4];
#pragma unroll
            for (int j = 0; j < 4; j++) {
                float a = hd.x * cWq[0 * 4 + j];
                a = fmaf(hd.y, cWq[1 * 4 + j], a);
                a = fmaf(hd.z, cWq[2 * 4 + j], a);
                a = fmaf(hd.w, cWq[3 * 4 + j], a);
                q[j] = a * INV_SQRT_DH;
            }
            float l0 = fmaf(q[0], k[0], q[1] * k[1]);
            float l1 = fmaf(q[2], k[2], q[3] * k[3]);
            float p0 = __expf(fminf(l0, 80.0f));
            float p1 = __expf(fminf(l1, 80.0f));

            float v[4];
#pragma unroll
            for (int j = 0; j < 4; j++) {
                float acc = msg[0] * cWv[0 * 4 + j];
#pragma unroll
                for (int r = 1; r < 8; r++) acc = fmaf(msg[r], cWv[r * 4 + j], acc);
                v[j] = acc;
            }
            float* na = accb + dstn * 8;
            atomicAdd(reinterpret_cast<float4*>(na),
                      make_float4(p0 * v[0], p0 * v[1], p1 * v[2], p1 * v[3]));
            atomicAdd(reinterpret_cast<float2*>(na + 4), make_float2(p0, p1));
        }
    }
}

// ---------------------------------------------------------------------------
// Finalize: per batch, h1 for marked nodes into a smem table, layer-1 over
// the listed edges for the 2 output nodes, then the linear head.
// ---------------------------------------------------------------------------
__global__ void __launch_bounds__(256) final_kernel(
        const float* __restrict__ x,
        const float* __restrict__ timestamp,
        const int*   __restrict__ src_index,
        const int*   __restrict__ dst_index,
        float* __restrict__ out) {
    __shared__ float4 sh1[N];        // 32 KB (only marked entries valid)
    __shared__ unsigned sbm[64];
    __shared__ float sacc[12];

    int b = blockIdx.x, t = threadIdx.x;
    if (t < 64) sbm[t] = g_bitmap[b * 64 + t];
    if (t < 12) sacc[t] = 0.0f;
    __syncthreads();

    const float4* xb = reinterpret_cast<const float4*>(x) + b * N;
    const float* accb = g_acc + (size_t)b * N * 8;
    float ts = __ldg(timestamp + b);

    // h1 for marked nodes
    for (int n = t; n < N; n += 256) {
        if (!((sbm[n >> 5] >> (n & 31)) & 1u)) continue;
        const float* na = accb + n * 8;
        float s0 = na[4], s1 = na[5];
        float r0 = (s0 == 0.0f) ? 1.0f : __frcp_rn(s0);
        float r1 = (s1 == 0.0f) ? 1.0f : __frcp_rn(s1);
        float at0 = na[0] * r0, at1 = na[1] * r0;
        float at2 = na[2] * r1, at3 = na[3] * r1;
        float4 xv = __ldg(xb + n);
        float hin[4] = {xv.x, xv.y, xv.z, xv.w};
        float h1[4];
#pragma unroll
        for (int j = 0; j < 4; j++) {
            float vv = hin[j] + cbo[j];
            vv = fmaf(at0, cWo[0 * 4 + j], vv);
            vv = fmaf(at1, cWo[1 * 4 + j], vv);
            vv = fmaf(at2, cWo[2 * 4 + j], vv);
            vv = fmaf(at3, cWo[3 * 4 + j], vv);
            h1[j] = fmaxf(vv, 0.0f);
        }
        sh1[n] = make_float4(h1[0], h1[1], h1[2], h1[3]);
    }
    __syncthreads();

    int out0 = __ldg(src_index + b);
    int out1 = __ldg(dst_index + b);
    int cnt0 = min(g_cnt[b * 2 + 0], LIST_CAP);
    int cnt1 = min(g_cnt[b * 2 + 1], LIST_CAP);
    const float* WkL = cWk + 32;
    const float* WvL = cWv + 32;
    const float* WqL = cWq + 16;

    for (int j = t; j < cnt0 + cnt1; j += 256) {
        int which = (j < cnt0) ? 0 : 1;
        int2 pl = g_list[(size_t)(b * 2 + which) * LIST_CAP +
                         (which == 0 ? j : j - cnt0)];
        int outn = (which == 0) ? out0 : out1;

        float dt = ts - __int_as_float(pl.y);
        float4 hs = sh1[pl.x];
        float msg[8];
        msg[0] = hs.x; msg[1] = hs.y; msg[2] = hs.z; msg[3] = hs.w;
#pragma unroll
        for (int r = 0; r < 4; r++) msg[4 + r] = __cosf(fmaf(dt, ctw[r], ctb[r]));

        float k[4];
#pragma unroll
        for (int c = 0; c < 4; c++) {
            float acc = msg[0] * WkL[0 * 4 + c];
#pragma unroll
            for (int r = 1; r < 8; r++) acc = fmaf(msg[r], WkL[r * 4 + c], acc);
            k[c] = acc;
        }
        float4 hd = sh1[outn];
        float q[4];
#pragma unroll
        for (int c = 0; c < 4; c++) {
            float a = hd.x * WqL[0 * 4 + c];
            a = fmaf(hd.y, WqL[1 * 4 + c], a);
            a = fmaf(hd.z, WqL[2 * 4 + c], a);
            a = fmaf(hd.w, WqL[3 * 4 + c], a);
            q[c] = a * INV_SQRT_DH;
        }
        float l0 = fmaf(q[0], k[0], q[1] * k[1]);
        float l1 = fmaf(q[2], k[2], q[3] * k[3]);
        float p0 = __expf(fminf(l0, 80.0f));
        float p1 = __expf(fminf(l1, 80.0f));

        float v[4];
#pragma unroll
        for (int c = 0; c < 4; c++) {
            float acc = msg[0] * WvL[0 * 4 + c];
#pragma unroll
            for (int r = 1; r < 8; r++) acc = fmaf(msg[r], WvL[r * 4 + c], acc);
            v[c] = acc;
        }
        float* na = sacc + which * 6;
        atomicAdd(na + 0, p0);
        atomicAdd(na + 1, p1);
        atomicAdd(na + 2, p0 * v[0]);
        atomicAdd(na + 3, p0 * v[1]);
        atomicAdd(na + 4, p1 * v[2]);
        atomicAdd(na + 5, p1 * v[3]);
    }
    __syncthreads();

    if (t == 0) {
        float f[12];
        const float* WoL = cWo + 16;
        const float* boL = cbo + 4;
#pragma unroll
        for (int w = 0; w < 2; w++) {
            int outn = (w == 0) ? out0 : out1;
            const float* na = sacc + w * 6;
            float s0 = na[0], s1 = na[1];
            float r0 = (s0 == 0.0f) ? 1.0f : __frcp_rn(s0);
            float r1 = (s1 == 0.0f) ? 1.0f : __frcp_rn(s1);
            float at0 = na[2] * r0, at1 = na[3] * r0;
            float at2 = na[4] * r1, at3 = na[5] * r1;
            float4 h1v = sh1[outn];
            float hin[4] = {h1v.x, h1v.y, h1v.z, h1v.w};
#pragma unroll
            for (int j = 0; j < 4; j++) {
                float vv = hin[j] + boL[j];
                vv = fmaf(at0, WoL[0 * 4 + j], vv);
                vv = fmaf(at1, WoL[1 * 4 + j], vv);
                vv = fmaf(at2, WoL[2 * 4 + j], vv);
                vv = fmaf(at3, WoL[3 * 4 + j], vv);
                f[w * 4 + j] = fmaxf(vv, 0.0f);
            }
        }
#pragma unroll
        for (int j = 0; j < 4; j++) f[8 + j] = cosf(fmaf(ts, ctw[j], ctb[j]));
#pragma unroll
        for (int c = 0; c < 2; c++) {
            float acc = cblin[c];
#pragma unroll
            for (int i = 0; i < 12; i++) acc = fmaf(f[i], cWlin[i * 2 + c], acc);
            out[b * 2 + c] = acc;
        }
    }
}

} // anonymous namespace

extern "C" void kernel_launch(void* const* d_in, const int* in_sizes, int n_in,
                              void* d_out, int out_size) {
    const float* x          = (const float*)d_in[0];
    const int*   edge_index = (const int*)  d_in[1];
    const float* edge_time  = (const float*)d_in[2];
    const float* timestamp  = (const float*)d_in[3];
    const int*   src_index  = (const int*)  d_in[4];
    const int*   dst_index  = (const int*)  d_in[5];
    float* out = (float*)d_out;

    // Stage all weights into constant memory (device-to-device, capturable).
    cudaMemcpyToSymbolAsync(cWq,   d_in[8],  2 * 16 * 4, 0, cudaMemcpyDeviceToDevice);
    cudaMemcpyToSymbolAsync(cWk,   d_in[9],  2 * 32 * 4, 0, cudaMemcpyDeviceToDevice);
    cudaMemcpyToSymbolAsync(cWv,   d_in[10], 2 * 32 * 4, 0, cudaMemcpyDeviceToDevice);
    cudaMemcpyToSymbolAsync(cWo,   d_in[11], 2 * 16 * 4, 0, cudaMemcpyDeviceToDevice);
    cudaMemcpyToSymbolAsync(cbo,   d_in[12], 2 * 4 * 4,  0, cudaMemcpyDeviceToDevice);
    cudaMemcpyToSymbolAsync(ctw,   d_in[6],  4 * 4,      0, cudaMemcpyDeviceToDevice);
    cudaMemcpyToSymbolAsync(ctb,   d_in[7],  4 * 4,      0, cudaMemcpyDeviceToDevice);
    cudaMemcpyToSymbolAsync(cWlin, d_in[13], 24 * 4,     0, cudaMemcpyDeviceToDevice);
    cudaMemcpyToSymbolAsync(cblin, d_in[14], 2 * 4,      0, cudaMemcpyDeviceToDevice);

    zero_kernel<<<B, 64>>>(src_index, dst_index);
    mark_kernel<<<B * SPLIT, 256>>>(edge_index, src_index, dst_index);
    scan_kernel<<<B * SPLIT, 256>>>(x, edge_index, edge_time, timestamp,
                                    src_index, dst_index);
    final_kernel<<<B, 256>>>(x, timestamp, src_index, dst_index, out);
}